// round 17
// baseline (speedup 1.0000x reference)
#include <cuda_runtime.h>

#define NB    8192     // B*N total rows
#define NPTS  4096     // nodes per batch
#define FDIM  64
#define KSEL  21       // k+1 (drop the smallest afterwards)
#define TPB   128      // 4 warps = 4 queries per block
#define GR    24       // grid resolution per dim
#define NC    (GR*GR*GR)
#define CELLH 0.5f
#define INVH  2.0f
#define ORIG  (-6.0f)
#define CAP   2048     // max gathered candidates per query
#define SCAN_T 512
#define CHUNKC (NC/SCAN_T)     // 27

typedef unsigned long long u64;

// ---------------- scratch (device globals; no allocation allowed) ----------
__device__ float4 g_pos4[NB];          // (x,y,z,sq)
__device__ float2 g_Whp[NB * 32];      // packed: [row][lane] = (Wh[l], Wh[l+32])
__device__ float  g_f1[NB];
__device__ float  g_f2[NB];
__device__ float  g_base[NB * FDIM];   // relu(pos@Wp + bp)
__device__ int    g_cnt[2][NC];        // per-cell point counts
__device__ int2   g_range[2][NC];      // (start, count)
__device__ int    g_cur[2][NC];        // scatter cursors
__device__ unsigned short g_pts[2][NPTS];   // point idx sorted by cell

__device__ __forceinline__ unsigned int fkey(float f) {
    unsigned int u = __float_as_uint(f);
    return u ^ (0x80000000u | (unsigned int)((int)u >> 31));
}
__device__ __forceinline__ float ikey(unsigned int k) {
    unsigned int o = (k & 0x80000000u) ? (k ^ 0x80000000u) : ~k;
    return __uint_as_float(o);
}
__device__ __forceinline__ int cellco(float v) {
    int c = (int)floorf((v - ORIG) * INVH);
    return min(max(c, 0), GR - 1);
}
// packed element: key<<13 | idx<<1 | flag (flag only on sentinels)
__device__ __forceinline__ u64 pe(unsigned int key, unsigned int idx) {
    return (((u64)key) << 13) | (idx << 1);
}
#define INS64(kk, cc)                                     \
    {                                                     \
        bool _c = (cc) < (kk);                            \
        u64 _mn = _c ? (cc) : (kk);                       \
        u64 _mx = _c ? (kk) : (cc);                       \
        (kk) = _mn;  (cc) = _mx;                          \
    }

// ---------------- kernel 0: reset cell counts -------------------------------
__global__ void zero_kernel() {
    int i = blockIdx.x * 1024 + threadIdx.x;
    int* p = &g_cnt[0][0];
    if (i < 2 * NC) p[i] = 0;
}

// ---------------- kernel A: per-node prep (4 rows / 256-thread block) ------
__global__ void __launch_bounds__(256)
prep_kernel(const float* __restrict__ x,
            const float* __restrict__ pos,
            const float* __restrict__ W,
            const float* __restrict__ a,
            const float* __restrict__ Wp,
            const float* __restrict__ bp) {
    int t   = threadIdx.x;
    int r   = t >> 6;            // row slot 0..3
    int j   = t & 63;            // feature 0..63
    int row = blockIdx.x * 4 + r;
    __shared__ float xs[4][FDIM];
    __shared__ float red[4][4];

    xs[r][j] = x[row * FDIM + j];
    __syncthreads();

    float acc = 0.f;
#pragma unroll 16
    for (int i = 0; i < FDIM; i++)
        acc += xs[r][i] * W[i * FDIM + j];
    {
        float* wp = (float*)&g_Whp[row * 32 + (j & 31)];
        wp[j >> 5] = acc;
    }

    float p1 = acc * a[j];
    float p2 = acc * a[FDIM + j];
#pragma unroll
    for (int off = 16; off; off >>= 1) {
        p1 += __shfl_down_sync(0xffffffffu, p1, off);
        p2 += __shfl_down_sync(0xffffffffu, p2, off);
    }
    int lane = j & 31, half = j >> 5;
    if (lane == 0) { red[r][half] = p1; red[r][2 + half] = p2; }

    float px = pos[row * 3 + 0];
    float py = pos[row * 3 + 1];
    float pz = pos[row * 3 + 2];
    float bj = px * Wp[j] + py * Wp[FDIM + j] + pz * Wp[2 * FDIM + j] + bp[j];
    g_base[row * FDIM + j] = bj > 0.f ? bj : 0.f;

    __syncthreads();
    if (j == 0) {
        g_f1[row] = red[r][0] + red[r][1];
        g_f2[row] = red[r][2] + red[r][3];
        float sq  = px * px + py * py + pz * pz;
        g_pos4[row] = make_float4(px, py, pz, sq);
        int cid = (cellco(pz) * GR + cellco(py)) * GR + cellco(px);
        atomicAdd(&g_cnt[row >> 12][cid], 1);
    }
}

// ---------------- kernel B: prefix scan over cells (1 block / batch) --------
__global__ void __launch_bounds__(SCAN_T)
scan_kernel() {
    int b = blockIdx.x, t = threadIdx.x;
    __shared__ int ps[SCAN_T];
    int base = t * CHUNKC, sum = 0;
#pragma unroll 9
    for (int i = 0; i < CHUNKC; i++) sum += g_cnt[b][base + i];
    ps[t] = sum;
    __syncthreads();
    for (int off = 1; off < SCAN_T; off <<= 1) {
        int v = (t >= off) ? ps[t - off] : 0;
        __syncthreads();
        ps[t] += v;
        __syncthreads();
    }
    int run = (t > 0) ? ps[t - 1] : 0;
    for (int i = 0; i < CHUNKC; i++) {
        int c = g_cnt[b][base + i];
        g_range[b][base + i] = make_int2(run, c);
        g_cur[b][base + i] = run;
        run += c;
    }
}

// ---------------- kernel C: scatter points into cell lists ------------------
__global__ void __launch_bounds__(256)
scatter_kernel() {
    int row = blockIdx.x * 256 + threadIdx.x;
    float4 p = g_pos4[row];
    int b = row >> 12;
    int cid = (cellco(p.z) * GR + cellco(p.y)) * GR + cellco(p.x);
    int pos = atomicAdd(&g_cur[b][cid], 1);
    g_pts[b][pos] = (unsigned short)(row & (NPTS - 1));
}

// ---------------- warp-cooperative shell gather -----------------------------
__device__ __forceinline__ void scan_shell(
    int s, int cx, int cy, int cz, int b, int lane,
    unsigned short* lst, int& len, bool& ovf)
{
    for (int dz = -s; dz <= s; dz++) {
        int zz = cz + dz;
        if ((unsigned)zz >= GR) continue;
        for (int dy = -s; dy <= s; dy++) {
            int yy = cy + dy;
            if ((unsigned)yy >= GR) continue;
            bool face = (dz == -s || dz == s || dy == -s || dy == s);
            int step = (face || s == 0) ? 1 : (2 * s);
            for (int dx = -s; dx <= s; dx += step) {
                int xx = cx + dx;
                if ((unsigned)xx >= GR) continue;
                int cid = (zz * GR + yy) * GR + xx;
                int2 rg = g_range[b][cid];
                if (rg.y == 0) continue;
                if (len + rg.y > CAP) { ovf = true; return; }
                for (int t = lane; t < rg.y; t += 32)
                    lst[len + t] = g_pts[b][rg.x + t];
                len += rg.y;
            }
        }
    }
}

// ---------------- exact warp selection over a candidate list ---------------
// Per lane: u64 (key,idx)-packed top-3 + 4th-element sentinel; 21 REDUX
// merge rounds with single-lane refill on sentinel fire. lst==NULL means
// identity list (full scan over len candidates).
__device__ __forceinline__ void warp_select(
    const unsigned short* lst, int len, const float4* pb, float4 q,
    int lane, unsigned int& nbr, float& last_d2key)
{
    const unsigned FULL = 0xffffffffu;
    u64 e0 = ~0ull, e1 = ~0ull, e2 = ~0ull, e3 = ~0ull;
    for (int j = lane; j < len; j += 32) {
        int idx = lst ? (int)lst[j] : j;
        float4 p = pb[idx];
        float d = fmaf(-2.f, fmaf(q.z, p.z, fmaf(q.y, p.y, q.x * p.x)), p.w);
        u64 c = pe(fkey(d), (unsigned)idx);
        INS64(e0, c) INS64(e1, c) INS64(e2, c)
        e3 = c < e3 ? c : e3;
    }
    u64 head = e0, L1 = e1, L2 = e2;
    u64 sent = (e3 == ~0ull) ? ~0ull : (e3 | 1ull);
    int hp = 1, r = 0;
    while (r < KSEL) {
        unsigned hi = (unsigned)(head >> 32), lo = (unsigned)head;
        unsigned whi = __reduce_min_sync(FULL, hi);
        unsigned clo = (hi == whi) ? lo : 0xFFFFFFFFu;
        unsigned wlo = __reduce_min_sync(FULL, clo);
        bool mine = (hi == whi) && (lo == wlo);
        u64 wpk = (((u64)whi) << 32) | wlo;
        bool sfire = mine && (wpk & 1ull);
        if (__ballot_sync(FULL, sfire)) {
            if (sfire) {
                u64 cut = L2;
                u64 k0 = ~0ull, k1 = ~0ull, k2 = ~0ull, k3 = ~0ull;
                for (int j = lane; j < len; j += 32) {
                    int idx = lst ? (int)lst[j] : j;
                    float4 p = pb[idx];
                    float d = fmaf(-2.f,
                                   fmaf(q.z, p.z, fmaf(q.y, p.y, q.x * p.x)),
                                   p.w);
                    u64 ev = pe(fkey(d), (unsigned)idx);
                    u64 c = (ev > cut) ? ev : ~0ull;
                    INS64(k0, c) INS64(k1, c) INS64(k2, c)
                    k3 = c < k3 ? c : k3;
                }
                head = k0; L1 = k1; L2 = k2;
                sent = (k3 == ~0ull) ? ~0ull : (k3 | 1ull);
                hp = 1;
            }
            continue;                // retry this round
        }
        unsigned m = (unsigned)((wpk >> 1) & 0xFFFull);
        if (lane == r - 1) nbr = m;  // rounds 1..20 record neighbors
        if (r == KSEL - 1) last_d2key = ikey((unsigned)(wpk >> 13));
        if (mine) { head = (hp == 1) ? L1 : (hp == 2) ? L2 : sent; hp++; }
        r++;
    }
}

// ---------------- kernel D: warp-per-query grid kNN(21) + attention --------
__global__ void __launch_bounds__(TPB, 8)
knn_attn_kernel(float* __restrict__ out) {
    __shared__ unsigned short slist[TPB / 32][CAP];
    const unsigned FULL = 0xffffffffu;
    int lane = threadIdx.x & 31;
    int wid  = threadIdx.x >> 5;
    int row  = blockIdx.x * (TPB / 32) + wid;
    int browbase = (row >> 12) << 12;
    const float4* pb = g_pos4 + browbase;
    float4 q = g_pos4[row];
    int b = row >> 12;
    unsigned short* lst = slist[wid];

    int cx = cellco(q.x), cy = cellco(q.y), cz = cellco(q.z);
    // L-inf shortfall of q outside its (clamped) cell box (0 when in range)
    float bx = ORIG + cx * CELLH, by = ORIG + cy * CELLH, bz = ORIG + cz * CELLH;
    float dq = 0.f;
    dq = fmaxf(dq, fmaxf(bx - q.x, q.x - (bx + CELLH)));
    dq = fmaxf(dq, fmaxf(by - q.y, q.y - (by + CELLH)));
    dq = fmaxf(dq, fmaxf(bz - q.z, q.z - (bz + CELLH)));
    dq = fmaxf(dq, 0.f);

    // ---- phase A: expand shells until >= KSEL candidates gathered ---------
    int len = 0, s = 0;
    bool ovf = false;
    while (len < KSEL && !ovf && s <= 2 * GR) {
        scan_shell(s, cx, cy, cz, b, lane, lst, len, ovf);
        s++;
    }
    __syncwarp();

    unsigned int nbr = 0;
    float lastkey = 0.f;
    if (!ovf) warp_select(lst, len, pb, q, lane, nbr, lastkey);

    // ---- phase C: certified expansion until geometry excludes the rest ----
    float bd2 = lastkey + q.w + 1e-4f;      // 21st d2 + safety margin
    int lenA = len;
    while (!ovf) {
        float md = fmaxf((float)(s - 1) * CELLH - dq, 0.f);
        if (md * md > bd2) break;
        scan_shell(s, cx, cy, cz, b, lane, lst, len, ovf);
        s++;
    }
    if (ovf) {
        // full exact fallback over all points (identity list)
        warp_select((const unsigned short*)0, NPTS, pb, q, lane, nbr, lastkey);
    } else if (len > lenA) {
        __syncwarp();
        warp_select(lst, len, pb, q, lane, nbr, lastkey);
    }

    // ---- softmax over the 20 neighbors (in-warp) --------------------------
    float e = -1e30f;
    if (lane < KSEL - 1) {
        float val = g_f1[row] + g_f2[browbase + (int)nbr];
        e = val > 0.f ? val : 0.2f * val;            // leaky relu 0.2
    }
    float mx = e;
#pragma unroll
    for (int off = 16; off; off >>= 1)
        mx = fmaxf(mx, __shfl_xor_sync(FULL, mx, off));
    float ex = (lane < KSEL - 1) ? expf(e - mx) : 0.f;
    float sm = ex;
#pragma unroll
    for (int off = 16; off; off >>= 1)
        sm += __shfl_xor_sync(FULL, sm, off);
    float attn = ex / sm;                            // valid on lanes < 20

    // ---- weighted Wh gather + base + elu (2 features per lane) ------------
    float acc0 = g_base[row * FDIM + lane];
    float acc1 = g_base[row * FDIM + 32 + lane];
#pragma unroll
    for (int j = 0; j < KSEL - 1; j++) {
        int   mj = (int)__shfl_sync(FULL, nbr, j);
        float aj = __shfl_sync(FULL, attn, j);
        float2 wv = g_Whp[(browbase + mj) * 32 + lane];
        acc0 = fmaf(aj, wv.x, acc0);
        acc1 = fmaf(aj, wv.y, acc1);
    }
    out[row * FDIM + lane]      = acc0 > 0.f ? acc0 : expm1f(acc0);
    out[row * FDIM + 32 + lane] = acc1 > 0.f ? acc1 : expm1f(acc1);
}

// ---------------- launch ----------------------------------------------------
extern "C" void kernel_launch(void* const* d_in, const int* in_sizes, int n_in,
                              void* d_out, int out_size) {
    (void)in_sizes; (void)n_in; (void)out_size;
    const float* x   = (const float*)d_in[0];
    const float* pos = (const float*)d_in[1];
    const float* W   = (const float*)d_in[2];
    const float* a   = (const float*)d_in[3];
    const float* Wp  = (const float*)d_in[4];
    const float* bp  = (const float*)d_in[5];
    float* out = (float*)d_out;

    zero_kernel<<<(2 * NC + 1023) / 1024, 1024>>>();
    prep_kernel<<<NB / 4, 256>>>(x, pos, W, a, Wp, bp);
    scan_kernel<<<2, SCAN_T>>>();
    scatter_kernel<<<NB / 256, 256>>>();
    knn_attn_kernel<<<NB / (TPB / 32), TPB>>>(out);
}